// round 1
// baseline (speedup 1.0000x reference)
#include <cuda_runtime.h>
#include <cstdint>

#define B_  64
#define HW_ 4096
#define C_  128
#define P_  64
#define NCHUNK 32          // chunks per batch in z-reduction
#define TM  128            // GEMM rows per block

// Scratch (allocation-free rule: device globals)
__device__ float g_zsum[(size_t)B_ * NCHUNK * C_];   // 1 MB
__device__ float g_z2[(size_t)B_ * NCHUNK];

// ---------- packed f32x2 helpers (Blackwell FFMA2, PTX-only) ----------
__device__ __forceinline__ unsigned long long pack2(float a, float b) {
    unsigned long long r;
    asm("mov.b64 %0, {%1,%2};" : "=l"(r) : "f"(a), "f"(b));
    return r;
}
__device__ __forceinline__ void unpack2(unsigned long long v, float& a, float& b) {
    asm("mov.b64 {%0,%1}, %2;" : "=f"(a), "=f"(b) : "l"(v));
}
__device__ __forceinline__ unsigned long long fma2(unsigned long long a,
                                                   unsigned long long b,
                                                   unsigned long long c) {
    unsigned long long r;
    asm("fma.rn.f32x2 %0, %1, %2, %3;" : "=l"(r) : "l"(a), "l"(b), "l"(c));
    return r;
}

// ---------- Kernel 1: z reduction (zsum[b][c], z2[b]) ----------
// grid (NCHUNK, B_), block 256. Each block: 128 HW-rows x 128 C of z.
__global__ __launch_bounds__(256)
void zreduce_kernel(const float* __restrict__ z) {
    const int chunk = blockIdx.x;
    const int b     = blockIdx.y;
    const int tid   = threadIdx.x;
    const float4* base =
        (const float4*)(z + ((size_t)b * HW_ + (size_t)chunk * 128) * C_);

    const int cq = tid & 31;   // c-quad (4 floats)
    const int rg = tid >> 5;   // row group 0..7

    float4 acc = make_float4(0.f, 0.f, 0.f, 0.f);
    float z2 = 0.f;
    #pragma unroll
    for (int j = 0; j < 16; ++j) {
        float4 v = base[(size_t)(rg + 8 * j) * (C_ / 4) + cq];
        acc.x += v.x; acc.y += v.y; acc.z += v.z; acc.w += v.w;
        z2 += v.x * v.x + v.y * v.y + v.z * v.z + v.w * v.w;
    }

    __shared__ float4 sred[256];
    __shared__ float  sz2[256];
    sred[tid] = acc;
    sz2[tid]  = z2;
    __syncthreads();

    if (rg == 0) {
        float4 t = sred[cq];
        #pragma unroll
        for (int g = 1; g < 8; ++g) {
            float4 v = sred[g * 32 + cq];
            t.x += v.x; t.y += v.y; t.z += v.z; t.w += v.w;
        }
        ((float4*)(g_zsum + ((size_t)b * NCHUNK + chunk) * C_))[cq] = t;
    }

    // block-reduce z2
    for (int off = 128; off > 0; off >>= 1) {
        if (tid < off) sz2[tid] += sz2[tid + off];
        __syncthreads();
    }
    if (tid == 0) g_z2[(size_t)b * NCHUNK + chunk] = sz2[0];
}

// ---------- Kernel 2: out = s @ k (M=262144, K=64, N=128), fp32 via FFMA2 ----------
// grid M/TM = 2048, block 256, dyn smem = 64 KB (k 32 KB + transposed s-tile 32 KB)
__global__ __launch_bounds__(256, 2)
void gemm_kernel(const float* __restrict__ s, const float* __restrict__ kk,
                 float* __restrict__ out) {
    extern __shared__ float smem[];
    float* sK  = smem;              // [P_][C_]   64x128
    float* sSt = smem + P_ * C_;    // [P_][TM]   transposed s tile

    const int tid = threadIdx.x;
    const size_t m0 = (size_t)blockIdx.x * TM;

    // stage k (8192 floats = 2048 float4)
    {
        const float4* src = (const float4*)kk;
        float4* dst = (float4*)sK;
        #pragma unroll
        for (int i = 0; i < (P_ * C_ / 4) / 256; ++i)
            dst[tid + i * 256] = src[tid + i * 256];
    }
    // stage s tile transposed: sSt[p][r] = s[m0+r][p]
    {
        #pragma unroll
        for (int i = 0; i < (TM * P_ / 4) / 256; ++i) {
            int idx = tid + i * 256;
            int r  = idx >> 4;       // / (P_/4)
            int pq = idx & 15;
            float4 v = ((const float4*)(s + (m0 + r) * P_))[pq];
            int p = pq * 4;
            sSt[(p + 0) * TM + r] = v.x;
            sSt[(p + 1) * TM + r] = v.y;
            sSt[(p + 2) * TM + r] = v.z;
            sSt[(p + 3) * TM + r] = v.w;
        }
    }
    __syncthreads();

    const int col_t = tid & 15;   // 16 threads across N
    const int row_t = tid >> 4;   // 16 thread-rows
    const int c0 = col_t * 8;

    unsigned long long acc[8][4];
    #pragma unroll
    for (int i = 0; i < 8; ++i)
        #pragma unroll
        for (int j = 0; j < 4; ++j) acc[i][j] = 0ull;

    #pragma unroll 4
    for (int p = 0; p < P_; ++p) {
        float4 ka = *(const float4*)(sK + p * C_ + c0);
        float4 kb = *(const float4*)(sK + p * C_ + c0 + 4);
        unsigned long long kp[4];
        kp[0] = pack2(ka.x, ka.y);
        kp[1] = pack2(ka.z, ka.w);
        kp[2] = pack2(kb.x, kb.y);
        kp[3] = pack2(kb.z, kb.w);
        #pragma unroll
        for (int i = 0; i < 8; ++i) {
            float sv = sSt[p * TM + row_t + 16 * i];
            unsigned long long s2 = pack2(sv, sv);
            #pragma unroll
            for (int j = 0; j < 4; ++j) acc[i][j] = fma2(s2, kp[j], acc[i][j]);
        }
    }

    #pragma unroll
    for (int i = 0; i < 8; ++i) {
        size_t row = m0 + row_t + 16 * i;
        float4 o0, o1;
        unpack2(acc[i][0], o0.x, o0.y);
        unpack2(acc[i][1], o0.z, o0.w);
        unpack2(acc[i][2], o1.x, o1.y);
        unpack2(acc[i][3], o1.z, o1.w);
        float4* dst = (float4*)(out + row * C_ + c0);
        dst[0] = o0;
        dst[1] = o1;
    }
}

// ---------- Kernel 3: distance[b][p] ----------
// grid B_, block 128
__global__ __launch_bounds__(128)
void dist_kernel(const float* __restrict__ kk, float* __restrict__ dist) {
    const int b = blockIdx.x;
    const int tid = threadIdx.x;
    __shared__ float zs[C_];
    __shared__ float z2s;

    float a = 0.f;
    #pragma unroll
    for (int ch = 0; ch < NCHUNK; ++ch)
        a += g_zsum[((size_t)b * NCHUNK + ch) * C_ + tid];
    zs[tid] = a;

    if (tid < 32) {
        float t = g_z2[(size_t)b * NCHUNK + tid];
        #pragma unroll
        for (int off = 16; off > 0; off >>= 1)
            t += __shfl_down_sync(0xffffffffu, t, off);
        if (tid == 0) z2s = t;
    }
    __syncthreads();

    if (tid < P_) {
        const float* kp = kk + (size_t)tid * C_;
        float dot = 0.f, k2 = 0.f;
        #pragma unroll 8
        for (int c = 0; c < C_; ++c) {
            float kv = kp[c];
            dot += zs[c] * kv;
            k2  += kv * kv;
        }
        dist[(size_t)b * P_ + tid] = z2s - 2.f * dot + (float)HW_ * k2;
    }
}

// ---------- launch ----------
extern "C" void kernel_launch(void* const* d_in, const int* in_sizes, int n_in,
                              void* d_out, int out_size) {
    const float* z = (const float*)d_in[0];   // (B,H,W,C)
    const float* s = (const float*)d_in[1];   // (B,H,W,P)
    const float* k = (const float*)d_in[2];   // (P,1,1,C)
    float* out  = (float*)d_out;                       // (B,H,W,C)
    float* dist = out + (size_t)in_sizes[0];           // (B,P) after out

    static bool attr_set = false;
    if (!attr_set) {
        cudaFuncSetAttribute(gemm_kernel,
                             cudaFuncAttributeMaxDynamicSharedMemorySize,
                             (P_ * C_ + P_ * TM) * (int)sizeof(float));
        attr_set = true;
    }

    zreduce_kernel<<<dim3(NCHUNK, B_), 256>>>(z);
    gemm_kernel<<<(B_ * HW_) / TM, 256,
                  (P_ * C_ + P_ * TM) * sizeof(float)>>>(s, k, out);
    dist_kernel<<<B_, 128>>>(k, dist);
}

// round 8
// speedup vs baseline: 1.7316x; 1.7316x over previous
#include <cuda_runtime.h>
#include <cstdint>

#define B_  64
#define HW_ 4096
#define C_  128      // N
#define P_  64       // K
#define NCHUNK 32
#define TILE_M 128

#define PITCH_A 68    // s-tile smem pitch (floats): conflict-free A frag loads
#define PITCH_B 136   // k-tile smem pitch (floats): conflict-free B frag loads
#define SMEM_FLOATS (128 * PITCH_A + P_ * PITCH_B)

// ---------------- scratch ----------------
__device__ float g_zsum[(size_t)B_ * NCHUNK * C_];
__device__ float g_z2[(size_t)B_ * NCHUNK];

// ---------------- helpers ----------------
__device__ __forceinline__ uint32_t tf32_rna(float a) {
    uint32_t r;
    asm("cvt.rna.tf32.f32 %0, %1;" : "=r"(r) : "f"(a));
    return r;
}

__device__ __forceinline__ void mma_tf32(float* d, const uint32_t* a,
                                         uint32_t b0, uint32_t b1) {
    asm volatile(
        "mma.sync.aligned.m16n8k8.row.col.f32.tf32.tf32.f32 "
        "{%0,%1,%2,%3}, {%4,%5,%6,%7}, {%8,%9}, {%0,%1,%2,%3};"
        : "+f"(d[0]), "+f"(d[1]), "+f"(d[2]), "+f"(d[3])
        : "r"(a[0]), "r"(a[1]), "r"(a[2]), "r"(a[3]), "r"(b0), "r"(b1));
}

// ---------------- fused kernel: z-reduce + tf32 GEMM ----------------
// grid 2048, block 256 (8 warps). CTA bx: GEMM rows [bx*128, bx*128+128),
// z chunk (b = bx>>5, chunk = bx&31).
__global__ __launch_bounds__(256, 2)
void fused_kernel(const float* __restrict__ z, const float* __restrict__ s,
                  const float* __restrict__ kk, float* __restrict__ out) {
    extern __shared__ float sm[];
    float* sA = sm;                        // [128][PITCH_A] s tile
    float* sB = sm + 128 * PITCH_A;        // [P_][PITCH_B]  k

    __shared__ float4 sred[256];
    __shared__ float  sz2[256];

    const int tid  = threadIdx.x;
    const int wid  = tid >> 5;
    const int lane = tid & 31;
    const int bx   = blockIdx.x;
    const size_t m0 = (size_t)bx * TILE_M;

    // ---- stage s tile: 128 rows x 64 floats ----
    #pragma unroll
    for (int i = 0; i < 8; ++i) {
        const int idx = tid + i * 256;           // 0..2047 float4s
        const int r = idx >> 4, q = idx & 15;
        float4 v = ((const float4*)(s + (m0 + r) * P_))[q];
        *(float4*)(sA + r * PITCH_A + q * 4) = v;
    }
    // ---- stage k: 64 rows x 128 floats ----
    #pragma unroll
    for (int i = 0; i < 8; ++i) {
        const int idx = tid + i * 256;
        const int p = idx >> 5, q = idx & 31;
        float4 v = ((const float4*)(kk + (size_t)p * C_))[q];
        *(float4*)(sB + p * PITCH_B + q * 4) = v;
    }

    // ---- z reduction phase (overlaps with staging latency) ----
    {
        const int b     = bx >> 5;
        const int chunk = bx & 31;
        const float4* base =
            (const float4*)(z + ((size_t)b * HW_ + (size_t)chunk * 128) * C_);
        const int cq = tid & 31;
        const int rg = tid >> 5;

        float4 acc = make_float4(0.f, 0.f, 0.f, 0.f);
        float z2 = 0.f;
        #pragma unroll
        for (int j = 0; j < 16; ++j) {
            float4 v = base[(size_t)(rg + 8 * j) * (C_ / 4) + cq];
            acc.x += v.x; acc.y += v.y; acc.z += v.z; acc.w += v.w;
            z2 += v.x * v.x + v.y * v.y + v.z * v.z + v.w * v.w;
        }
        sred[tid] = acc;
        sz2[tid]  = z2;
        __syncthreads();

        if (rg == 0) {
            float4 t = sred[cq];
            #pragma unroll
            for (int g = 1; g < 8; ++g) {
                float4 v = sred[g * 32 + cq];
                t.x += v.x; t.y += v.y; t.z += v.z; t.w += v.w;
            }
            ((float4*)(g_zsum + ((size_t)b * NCHUNK + chunk) * C_))[cq] = t;
        }
        #pragma unroll
        for (int off = 128; off > 0; off >>= 1) {
            if (tid < off) sz2[tid] += sz2[tid + off];
            __syncthreads();
        }
        if (tid == 0) g_z2[(size_t)b * NCHUNK + chunk] = sz2[0];
    }
    __syncthreads();   // sA/sB staging complete

    // ---- MMA phase: warp grid 4(M) x 2(N); warp tile 32x64 ----
    const int warpM = wid & 3;
    const int warpN = wid >> 2;
    const int lq = lane >> 2;   // 0..7
    const int lr = lane & 3;    // 0..3

    float acc[2][8][4];
    #pragma unroll
    for (int mi = 0; mi < 2; ++mi)
        #pragma unroll
        for (int ni = 0; ni < 8; ++ni)
            #pragma unroll
            for (int j = 0; j < 4; ++j) acc[mi][ni][j] = 0.f;

    #pragma unroll
    for (int k0 = 0; k0 < P_; k0 += 8) {
        // A fragments (hi/lo) for the 2 m16 tiles
        uint32_t ah[2][4], al[2][4];
        #pragma unroll
        for (int mi = 0; mi < 2; ++mi) {
            const int r = warpM * 32 + mi * 16 + lq;
            const float* base = sA + r * PITCH_A + k0 + lr;
            const float a0 = base[0];
            const float a1 = base[8 * PITCH_A];
            const float a2 = base[4];
            const float a3 = base[8 * PITCH_A + 4];
            ah[mi][0] = tf32_rna(a0); al[mi][0] = tf32_rna(a0 - __uint_as_float(ah[mi][0]));
            ah[mi][1] = tf32_rna(a1); al[mi][1] = tf32_rna(a1 - __uint_as_float(ah[mi][1]));
            ah[mi][2] = tf32_rna(a2); al[mi][2] = tf32_rna(a2 - __uint_as_float(ah[mi][2]));
            ah[mi][3] = tf32_rna(a3); al[mi][3] = tf32_rna(a3 - __uint_as_float(ah[mi][3]));
        }
        #pragma unroll
        for (int ni = 0; ni < 8; ++ni) {
            const int c = warpN * 64 + ni * 8 + lq;
            const float b0 = sB[(k0 + lr) * PITCH_B + c];
            const float b1 = sB[(k0 + lr + 4) * PITCH_B + c];
            const uint32_t bh0 = tf32_rna(b0);
            const uint32_t bh1 = tf32_rna(b1);
            const uint32_t bl0 = tf32_rna(b0 - __uint_as_float(bh0));
            const uint32_t bl1 = tf32_rna(b1 - __uint_as_float(bh1));
            #pragma unroll
            for (int mi = 0; mi < 2; ++mi) {
                mma_tf32(acc[mi][ni], ah[mi], bh0, bh1);  // hi*hi
                mma_tf32(acc[mi][ni], ah[mi], bl0, bl1);  // hi*lo
                mma_tf32(acc[mi][ni], al[mi], bh0, bh1);  // lo*hi
            }
        }
    }

    // ---- epilogue: direct float2 stores ----
    #pragma unroll
    for (int mi = 0; mi < 2; ++mi) {
        const size_t row = m0 + warpM * 32 + mi * 16 + lq;
        #pragma unroll
        for (int ni = 0; ni < 8; ++ni) {
            const int col = warpN * 64 + ni * 8 + 2 * lr;
            *(float2*)(out + row * C_ + col) =
                make_float2(acc[mi][ni][0], acc[mi][ni][1]);
            *(float2*)(out + (row + 8) * C_ + col) =
                make_float2(acc[mi][ni][2], acc[mi][ni][3]);
        }
    }
}

// ---------------- Kernel 2: distance ----------------
__global__ __launch_bounds__(128)
void dist_kernel(const float* __restrict__ kk, float* __restrict__ dist) {
    const int b = blockIdx.x;
    const int tid = threadIdx.x;
    __shared__ float zs[C_];
    __shared__ float z2s;

    float a = 0.f;
    #pragma unroll
    for (int ch = 0; ch < NCHUNK; ++ch)
        a += g_zsum[((size_t)b * NCHUNK + ch) * C_ + tid];
    zs[tid] = a;

    if (tid < 32) {
        float t = g_z2[(size_t)b * NCHUNK + tid];
        #pragma unroll
        for (int off = 16; off > 0; off >>= 1)
            t += __shfl_down_sync(0xffffffffu, t, off);
        if (tid == 0) z2s = t;
    }
    __syncthreads();

    if (tid < P_) {
        const float* kp = kk + (size_t)tid * C_;
        float dot = 0.f, k2 = 0.f;
        #pragma unroll 8
        for (int c = 0; c < C_; ++c) {
            float kv = kp[c];
            dot += zs[c] * kv;
            k2  += kv * kv;
        }
        dist[(size_t)b * P_ + tid] = z2s - 2.f * dot + (float)HW_ * k2;
    }
}

// ---------------- launch ----------------
extern "C" void kernel_launch(void* const* d_in, const int* in_sizes, int n_in,
                              void* d_out, int out_size) {
    const float* z = (const float*)d_in[0];
    const float* s = (const float*)d_in[1];
    const float* k = (const float*)d_in[2];
    float* out  = (float*)d_out;
    float* dist = out + (size_t)in_sizes[0];

    static bool attr_set = false;
    if (!attr_set) {
        cudaFuncSetAttribute(fused_kernel,
                             cudaFuncAttributeMaxDynamicSharedMemorySize,
                             SMEM_FLOATS * (int)sizeof(float));
        attr_set = true;
    }

    fused_kernel<<<(B_ * HW_) / TILE_M, 256, SMEM_FLOATS * sizeof(float)>>>(
        z, s, k, out);
    dist_kernel<<<B_, 128>>>(k, dist);
}